// round 1
// baseline (speedup 1.0000x reference)
#include <cuda_runtime.h>
#include <math.h>

#define BB 4
#define CC 3
#define HH 1024
#define WW 1024
#define NBC 12          // B*C
#define G0 255
#define G1 127
#define G2 63
#define G3 31

// ---------------- scratch (device globals; no allocation allowed) ----------------
__device__ float dS0[4][NBC*G0*G0];   // level-0 box sums: Sg, Ss, Sgg, Sgs
__device__ float dS1[4][NBC*G1*G1];
__device__ float dS2[4][NBC*G2*G2];
__device__ float dF1[2][NBC*G1*G1];   // cov, var at level 1 (r=16)
__device__ float dF2[2][NBC*G2*G2];   // level 2 (r=32)
__device__ float dF3[2][NBC*G3*G3];   // level 3 (r=64)
__device__ float dAf[NBC*G0*G0];      // A
__device__ float dCf[NBC*G0*G0];      // b = my1 - A*mx1

// ---------------- kernel 1: level-0 box sums (r=8, s=4, VALID) ----------------
// Block: 256 threads, handles one (b,c) slab and a chunk of 16 output rows.
// Vertical composition: P[m] = sum over input rows 4m..4m+3; out[i] = P[i]+P[i+1].
__global__ __launch_bounds__(256) void boxsum_kernel(const float* __restrict__ guide,
                                                     const float* __restrict__ src) {
    __shared__ __align__(16) float shg[4 * 1024];
    __shared__ __align__(16) float shs[4 * 1024];
    const int t  = threadIdx.x;
    const int bc = blockIdx.y;
    const int i0 = blockIdx.x * 16;
    const int i1 = min(i0 + 16, 255);

    const float* gbase = guide + (size_t)bc * HH * WW;
    const float* sbase = src   + (size_t)bc * HH * WW;

    float qg = 0.f, qs = 0.f, qgg = 0.f, qgs = 0.f;   // previous partial P[m-1]

    for (int m = i0; m <= i1; ++m) {
        // load input rows 4m..4m+3 of guide and src (coalesced float4)
        const float4* gp = (const float4*)(gbase + (size_t)(4 * m) * WW);
        const float4* sp = (const float4*)(sbase + (size_t)(4 * m) * WW);
        float4* shg4 = (float4*)shg;
        float4* shs4 = (float4*)shs;
        #pragma unroll
        for (int k = 0; k < 4; ++k) {
            int idx = t + k * 256;
            shg4[idx] = gp[idx];
            shs4[idx] = sp[idx];
        }
        __syncthreads();

        if (t < 255) {
            float pg = 0.f, ps = 0.f, pgg = 0.f, pgs = 0.f;
            #pragma unroll
            for (int rr = 0; rr < 4; ++rr) {
                const float* g = shg + rr * 1024 + 4 * t;
                const float* s = shs + rr * 1024 + 4 * t;
                float4 ga = *(const float4*)(g);
                float4 gb = *(const float4*)(g + 4);
                float4 sa = *(const float4*)(s);
                float4 sb = *(const float4*)(s + 4);
                float gv[8] = {ga.x, ga.y, ga.z, ga.w, gb.x, gb.y, gb.z, gb.w};
                float sv[8] = {sa.x, sa.y, sa.z, sa.w, sb.x, sb.y, sb.z, sb.w};
                #pragma unroll
                for (int k = 0; k < 8; ++k) {
                    pg += gv[k];
                    ps += sv[k];
                    pgg = fmaf(gv[k], gv[k], pgg);
                    pgs = fmaf(gv[k], sv[k], pgs);
                }
            }
            if (m > i0) {
                int off = bc * G0 * G0 + (m - 1) * G0 + t;
                dS0[0][off] = qg + pg;
                dS0[1][off] = qs + ps;
                dS0[2][off] = qgg + pgg;
                dS0[3][off] = qgs + pgs;
            }
            qg = pg; qs = ps; qgg = pgg; qgs = pgs;
        }
        __syncthreads();
    }
}

// ---------------- kernel 2: pyramid level L from L-1; emit cov/var ----------------
template<int L>
__global__ __launch_bounds__(256) void pyr_kernel() {
    constexpr int   GIN  = (L == 1) ? G0 : (L == 2) ? G1 : G2;
    constexpr int   GOUT = (L == 1) ? G1 : (L == 2) ? G2 : G3;
    constexpr float INVN = (L == 1) ? (1.f/256.f) : (L == 2) ? (1.f/1024.f) : (1.f/4096.f);

    int idx = blockIdx.x * blockDim.x + threadIdx.x;
    int bc  = blockIdx.y;
    if (idx >= GOUT * GOUT) return;
    int i = idx / GOUT, j = idx - i * GOUT;

    const float *in0, *in1, *in2, *in3;
    if      constexpr (L == 1) { in0 = dS0[0]; in1 = dS0[1]; in2 = dS0[2]; in3 = dS0[3]; }
    else if constexpr (L == 2) { in0 = dS1[0]; in1 = dS1[1]; in2 = dS1[2]; in3 = dS1[3]; }
    else                       { in0 = dS2[0]; in1 = dS2[1]; in2 = dS2[2]; in3 = dS2[3]; }

    int p00 = bc * GIN * GIN + 2 * i * GIN + 2 * j;
    #define SUM4(p) ((p)[p00] + (p)[p00 + 2] + (p)[p00 + 2*GIN] + (p)[p00 + 2*GIN + 2])
    float sg  = SUM4(in0);
    float ss  = SUM4(in1);
    float sgg = SUM4(in2);
    float sgs = SUM4(in3);
    #undef SUM4

    int o = bc * GOUT * GOUT + idx;
    if      constexpr (L == 1) { dS1[0][o]=sg; dS1[1][o]=ss; dS1[2][o]=sgg; dS1[3][o]=sgs; }
    else if constexpr (L == 2) { dS2[0][o]=sg; dS2[1][o]=ss; dS2[2][o]=sgg; dS2[3][o]=sgs; }

    float mx = sg * INVN, my = ss * INVN;
    float cov = fmaf(-mx, my, sgs * INVN);
    float var = fmaf(-mx, mx, sgg * INVN);
    if      constexpr (L == 1) { dF1[0][o] = cov; dF1[1][o] = var; }
    else if constexpr (L == 2) { dF2[0][o] = cov; dF2[1][o] = var; }
    else                       { dF3[0][o] = cov; dF3[1][o] = var; }
}

// ---------------- bilinear (align_corners) sample of one level's cov/var ----------------
__device__ __forceinline__ void sampleLevel(const float* __restrict__ covP,
                                            const float* __restrict__ varP,
                                            int G, int b, int i, int j, float* xo) {
    float scale = (float)((double)(G - 1) / 254.0);
    float py = i * scale, px = j * scale;
    int iy = (int)py; if (iy > G - 2) iy = G - 2;
    int ix = (int)px; if (ix > G - 2) ix = G - 2;
    float wy = py - iy, wx = px - ix;
    #pragma unroll
    for (int c = 0; c < 3; ++c) {
        int base = (b * 3 + c) * G * G + iy * G + ix;
        {
            float v00 = covP[base],     v01 = covP[base + 1];
            float v10 = covP[base + G], v11 = covP[base + G + 1];
            float v0 = v00 + wx * (v01 - v00);
            float v1 = v10 + wx * (v11 - v10);
            xo[c] = v0 + wy * (v1 - v0);
        }
        {
            float v00 = varP[base],     v01 = varP[base + 1];
            float v10 = varP[base + G], v11 = varP[base + G + 1];
            float v0 = v00 + wx * (v01 - v00);
            float v1 = v10 + wx * (v11 - v10);
            xo[3 + c] = v0 + wy * (v1 - v0);
        }
    }
}

// ---------------- kernel 3: per-pixel MLP (24->48->48->3), writes A and b ----------------
// Grid: (255 rows, 4 batches); 256 threads, t<255 = column.
__global__ __launch_bounds__(256) void mlp_kernel(
    const float* __restrict__ w1, const float* __restrict__ g1, const float* __restrict__ b1,
    const float* __restrict__ rm1, const float* __restrict__ rv1,
    const float* __restrict__ w2, const float* __restrict__ g2, const float* __restrict__ b2,
    const float* __restrict__ rm2, const float* __restrict__ rv2,
    const float* __restrict__ w3) {

    __shared__ __align__(16) float sW1[48 * 24];
    __shared__ __align__(16) float sW2[48 * 48];
    __shared__ __align__(16) float sW3[3 * 48];
    __shared__ float sB1[48];
    __shared__ float sB2[48];

    const int t = threadIdx.x;
    if (t < 48) {
        float inv1 = g1[t] * rsqrtf(rv1[t] + 1e-5f);
        sB1[t] = fmaf(-rm1[t], inv1, b1[t]);
        #pragma unroll
        for (int c = 0; c < 24; ++c) sW1[t * 24 + c] = w1[t * 24 + c] * inv1;
        float inv2 = g2[t] * rsqrtf(rv2[t] + 1e-5f);
        sB2[t] = fmaf(-rm2[t], inv2, b2[t]);
        #pragma unroll
        for (int c = 0; c < 48; ++c) sW2[t * 48 + c] = w2[t * 48 + c] * inv2;
    }
    if (t < 3) {
        #pragma unroll
        for (int c = 0; c < 48; ++c) sW3[t * 48 + c] = w3[t * 48 + c];
    }
    __syncthreads();
    if (t >= 255) return;

    const int i = blockIdx.x;   // row in 255-grid
    const int b = blockIdx.y;   // batch
    const int j = t;

    float x[24], mx1[3], my1[3];
    // level 0 stats (N = 64)
    #pragma unroll
    for (int c = 0; c < 3; ++c) {
        int off = (b * 3 + c) * G0 * G0 + i * G0 + j;
        float sg  = dS0[0][off] * (1.f/64.f);
        float ss  = dS0[1][off] * (1.f/64.f);
        float sgg = dS0[2][off] * (1.f/64.f);
        float sgs = dS0[3][off] * (1.f/64.f);
        mx1[c] = sg; my1[c] = ss;
        x[c]     = fmaf(-sg, ss, sgs);   // cov1
        x[3 + c] = fmaf(-sg, sg, sgg);   // var1
    }
    sampleLevel(dF1[0], dF1[1], G1, b, i, j, &x[6]);
    sampleLevel(dF2[0], dF2[1], G2, b, i, j, &x[12]);
    sampleLevel(dF3[0], dF3[1], G3, b, i, j, &x[18]);

    // layer 1: 24 -> 48, BN folded, relu
    float h[48];
    #pragma unroll
    for (int o = 0; o < 48; ++o) {
        float acc = sB1[o];
        const float4* wr = (const float4*)&sW1[o * 24];
        #pragma unroll
        for (int c4 = 0; c4 < 6; ++c4) {
            float4 w = wr[c4];
            acc = fmaf(w.x, x[4*c4+0], acc);
            acc = fmaf(w.y, x[4*c4+1], acc);
            acc = fmaf(w.z, x[4*c4+2], acc);
            acc = fmaf(w.w, x[4*c4+3], acc);
        }
        h[o] = fmaxf(acc, 0.f);
    }
    // layer 2: 48 -> 48, BN folded, relu
    float h2[48];
    #pragma unroll
    for (int o = 0; o < 48; ++o) {
        float acc = sB2[o];
        const float4* wr = (const float4*)&sW2[o * 48];
        #pragma unroll
        for (int c4 = 0; c4 < 12; ++c4) {
            float4 w = wr[c4];
            acc = fmaf(w.x, h[4*c4+0], acc);
            acc = fmaf(w.y, h[4*c4+1], acc);
            acc = fmaf(w.z, h[4*c4+2], acc);
            acc = fmaf(w.w, h[4*c4+3], acc);
        }
        h2[o] = fmaxf(acc, 0.f);
    }
    // layer 3: 48 -> 3 (no BN, no bias)
    #pragma unroll
    for (int o = 0; o < 3; ++o) {
        float acc = 0.f;
        const float4* wr = (const float4*)&sW3[o * 48];
        #pragma unroll
        for (int c4 = 0; c4 < 12; ++c4) {
            float4 w = wr[c4];
            acc = fmaf(w.x, h2[4*c4+0], acc);
            acc = fmaf(w.y, h2[4*c4+1], acc);
            acc = fmaf(w.z, h2[4*c4+2], acc);
            acc = fmaf(w.w, h2[4*c4+3], acc);
        }
        int off = (b * 3 + o) * G0 * G0 + i * G0 + j;
        dAf[off] = acc;
        dCf[off] = fmaf(-acc, mx1[o], my1[o]);   // b = my1 - A*mx1
    }
}

// ---------------- kernel 4: upsample A,b (255->1024, align_corners) + affine ----------------
// Grid: (1024 rows, 12 bc planes); 256 threads * 4 px (float4).
__global__ __launch_bounds__(256) void final_kernel(const float* __restrict__ guide,
                                                    float* __restrict__ out) {
    __shared__ float sA[256];
    __shared__ float sC[256];
    const int y  = blockIdx.x;
    const int bc = blockIdx.y;
    const int t  = threadIdx.x;
    const float scale = (float)(254.0 / 1023.0);

    float py = y * scale;
    int iy = (int)py; if (iy > 253) iy = 253;
    float wy = py - iy;

    if (t < 255) {
        int b0 = bc * G0 * G0 + iy * G0 + t;
        float a0 = dAf[b0], a1 = dAf[b0 + G0];
        sA[t] = a0 + wy * (a1 - a0);
        float c0 = dCf[b0], c1 = dCf[b0 + G0];
        sC[t] = c0 + wy * (c1 - c0);
    }
    __syncthreads();

    size_t rowoff = ((size_t)bc * HH + y) * WW;
    float4 g = ((const float4*)(guide + rowoff))[t];
    float gv[4] = {g.x, g.y, g.z, g.w};
    float rv[4];
    #pragma unroll
    for (int k = 0; k < 4; ++k) {
        int xpix = 4 * t + k;
        float px = xpix * scale;
        int ix = (int)px; if (ix > 253) ix = 253;
        float wx = px - ix;
        float Av = sA[ix] + wx * (sA[ix + 1] - sA[ix]);
        float Cv = sC[ix] + wx * (sC[ix + 1] - sC[ix]);
        rv[k] = fmaf(Av, gv[k], Cv);
    }
    float4 r = {rv[0], rv[1], rv[2], rv[3]};
    ((float4*)(out + rowoff))[t] = r;
}

// ---------------- launch ----------------
extern "C" void kernel_launch(void* const* d_in, const int* in_sizes, int n_in,
                              void* d_out, int out_size) {
    const float* guide = (const float*)d_in[0];
    const float* src   = (const float*)d_in[1];
    const float* w1  = (const float*)d_in[2];
    const float* g1  = (const float*)d_in[3];
    const float* b1  = (const float*)d_in[4];
    const float* rm1 = (const float*)d_in[5];
    const float* rv1 = (const float*)d_in[6];
    const float* w2  = (const float*)d_in[7];
    const float* g2  = (const float*)d_in[8];
    const float* b2  = (const float*)d_in[9];
    const float* rm2 = (const float*)d_in[10];
    const float* rv2 = (const float*)d_in[11];
    const float* w3  = (const float*)d_in[12];
    float* out = (float*)d_out;

    boxsum_kernel<<<dim3(16, NBC), 256>>>(guide, src);
    pyr_kernel<1><<<dim3((G1*G1 + 255) / 256, NBC), 256>>>();
    pyr_kernel<2><<<dim3((G2*G2 + 255) / 256, NBC), 256>>>();
    pyr_kernel<3><<<dim3((G3*G3 + 255) / 256, NBC), 256>>>();
    mlp_kernel<<<dim3(G0, BB), 256>>>(w1, g1, b1, rm1, rv1, w2, g2, b2, rm2, rv2, w3);
    final_kernel<<<dim3(HH, NBC), 256>>>(guide, out);
}

// round 2
// speedup vs baseline: 1.0180x; 1.0180x over previous
#include <cuda_runtime.h>
#include <math.h>

#define BB 4
#define CC 3
#define HH 1024
#define WW 1024
#define NBC 12          // B*C
#define G0 255
#define G1 127
#define G2 63
#define G3 31

typedef unsigned long long ull;

// ---------------- f32x2 helpers (FFMA2 reachable only via PTX) ----------------
__device__ __forceinline__ ull pack2(float lo, float hi) {
    ull r; asm("mov.b64 %0, {%1,%2};" : "=l"(r) : "f"(lo), "f"(hi)); return r;
}
__device__ __forceinline__ float2 unpack2(ull v) {
    float2 r; asm("mov.b64 {%0,%1}, %2;" : "=f"(r.x), "=f"(r.y) : "l"(v)); return r;
}
__device__ __forceinline__ ull fma2(ull a, ull b, ull c) {
    ull d; asm("fma.rn.f32x2 %0, %1, %2, %3;" : "=l"(d) : "l"(a), "l"(b), "l"(c)); return d;
}
__device__ __forceinline__ ull relu2(ull v) {
    float2 t = unpack2(v);
    return pack2(fmaxf(t.x, 0.f), fmaxf(t.y, 0.f));
}

// ---------------- scratch (device globals; no allocation allowed) ----------------
__device__ float dS0[4][NBC*G0*G0];   // level-0 box sums: Sg, Ss, Sgg, Sgs
__device__ float dS1[4][NBC*G1*G1];
__device__ float dS2[4][NBC*G2*G2];
__device__ float dF1[2][NBC*G1*G1];   // cov, var at level 1 (r=16)
__device__ float dF2[2][NBC*G2*G2];   // level 2 (r=32)
__device__ float dF3[2][NBC*G3*G3];   // level 3 (r=64)
__device__ float dAf[NBC*G0*G0];      // A
__device__ float dCf[NBC*G0*G0];      // b = my1 - A*mx1

// ---------------- kernel 1: level-0 box sums (r=8, s=4, VALID) ----------------
// Grid (32, NBC): each block = 8 output rows of one (b,c) slab.
// P[m] = sum over input rows 4m..4m+3; out[i] = P[i]+P[i+1].
__global__ __launch_bounds__(256) void boxsum_kernel(const float* __restrict__ guide,
                                                     const float* __restrict__ src) {
    __shared__ __align__(16) float shg[4 * 1024];
    __shared__ __align__(16) float shs[4 * 1024];
    const int t  = threadIdx.x;
    const int bc = blockIdx.y;
    const int i0 = blockIdx.x * 8;
    const int i1 = min(i0 + 8, 255);

    const float* gbase = guide + (size_t)bc * HH * WW;
    const float* sbase = src   + (size_t)bc * HH * WW;

    float qg = 0.f, qs = 0.f, qgg = 0.f, qgs = 0.f;   // previous partial P[m-1]

    for (int m = i0; m <= i1; ++m) {
        const float4* gp = (const float4*)(gbase + (size_t)(4 * m) * WW);
        const float4* sp = (const float4*)(sbase + (size_t)(4 * m) * WW);
        float4* shg4 = (float4*)shg;
        float4* shs4 = (float4*)shs;
        #pragma unroll
        for (int k = 0; k < 4; ++k) {
            int idx = t + k * 256;
            shg4[idx] = gp[idx];
            shs4[idx] = sp[idx];
        }
        __syncthreads();

        if (t < 255) {
            float pg = 0.f, ps = 0.f, pgg = 0.f, pgs = 0.f;
            #pragma unroll
            for (int rr = 0; rr < 4; ++rr) {
                const float* g = shg + rr * 1024 + 4 * t;
                const float* s = shs + rr * 1024 + 4 * t;
                float4 ga = *(const float4*)(g);
                float4 gb = *(const float4*)(g + 4);
                float4 sa = *(const float4*)(s);
                float4 sb = *(const float4*)(s + 4);
                float gv[8] = {ga.x, ga.y, ga.z, ga.w, gb.x, gb.y, gb.z, gb.w};
                float sv[8] = {sa.x, sa.y, sa.z, sa.w, sb.x, sb.y, sb.z, sb.w};
                #pragma unroll
                for (int k = 0; k < 8; ++k) {
                    pg += gv[k];
                    ps += sv[k];
                    pgg = fmaf(gv[k], gv[k], pgg);
                    pgs = fmaf(gv[k], sv[k], pgs);
                }
            }
            if (m > i0) {
                int off = bc * G0 * G0 + (m - 1) * G0 + t;
                dS0[0][off] = qg + pg;
                dS0[1][off] = qs + ps;
                dS0[2][off] = qgg + pgg;
                dS0[3][off] = qgs + pgs;
            }
            qg = pg; qs = ps; qgg = pgg; qgs = pgs;
        }
        __syncthreads();
    }
}

// ---------------- pyramid step helper ----------------
__device__ __forceinline__ void pyr_step(const float* __restrict__ in0, const float* __restrict__ in1,
                                         const float* __restrict__ in2, const float* __restrict__ in3,
                                         float* s0, float* s1, float* s2, float* s3,
                                         float* fcov, float* fvar,
                                         int GIN, int GOUT, float INVN, int bc, int idx) {
    int i = idx / GOUT, j = idx - i * GOUT;
    int p00 = bc * GIN * GIN + 2 * i * GIN + 2 * j;
    #define SUM4(p) ((p)[p00] + (p)[p00 + 2] + (p)[p00 + 2*GIN] + (p)[p00 + 2*GIN + 2])
    float sg  = SUM4(in0);
    float ss  = SUM4(in1);
    float sgg = SUM4(in2);
    float sgs = SUM4(in3);
    #undef SUM4
    int o = bc * GOUT * GOUT + idx;
    if (s0) { s0[o] = sg; s1[o] = ss; s2[o] = sgg; s3[o] = sgs; }
    float mx = sg * INVN, my = ss * INVN;
    fcov[o] = fmaf(-mx, my, sgs * INVN);
    fvar[o] = fmaf(-mx, mx, sgg * INVN);
}

// ---------------- kernel 2a: level 1 (r=16) ----------------
__global__ __launch_bounds__(256) void pyr1_kernel() {
    int idx = blockIdx.x * blockDim.x + threadIdx.x;
    if (idx >= G1 * G1) return;
    pyr_step(dS0[0], dS0[1], dS0[2], dS0[3],
             dS1[0], dS1[1], dS1[2], dS1[3],
             dF1[0], dF1[1], G0, G1, 1.f/256.f, blockIdx.y, idx);
}

// ---------------- kernel 2b: levels 2 and 3 fused (one block per bc) ----------------
__global__ __launch_bounds__(256) void pyr23_kernel() {
    const int bc = blockIdx.x;
    for (int idx = threadIdx.x; idx < G2 * G2; idx += 256)
        pyr_step(dS1[0], dS1[1], dS1[2], dS1[3],
                 dS2[0], dS2[1], dS2[2], dS2[3],
                 dF2[0], dF2[1], G1, G2, 1.f/1024.f, bc, idx);
    __syncthreads();
    for (int idx = threadIdx.x; idx < G3 * G3; idx += 256)
        pyr_step(dS2[0], dS2[1], dS2[2], dS2[3],
                 (float*)0, (float*)0, (float*)0, (float*)0,
                 dF3[0], dF3[1], G2, G3, 1.f/4096.f, bc, idx);
}

// ---------------- bilinear sample of one level (two batches packed) ----------------
__device__ __forceinline__ float bilin(const float* __restrict__ p, int base, int G,
                                       float wx, float wy) {
    float v00 = p[base],     v01 = p[base + 1];
    float v10 = p[base + G], v11 = p[base + G + 1];
    float v0 = v00 + wx * (v01 - v00);
    float v1 = v10 + wx * (v11 - v10);
    return v0 + wy * (v1 - v0);
}

__device__ __forceinline__ void sampleLevel2(const float* __restrict__ covP,
                                             const float* __restrict__ varP,
                                             int G, int bA, int bBt, int i, int j, ull* xo) {
    float scale = (float)((double)(G - 1) / 254.0);
    float py = i * scale, px = j * scale;
    int iy = (int)py; if (iy > G - 2) iy = G - 2;
    int ix = (int)px; if (ix > G - 2) ix = G - 2;
    float wy = py - iy, wx = px - ix;
    #pragma unroll
    for (int c = 0; c < 3; ++c) {
        int baseA = ((bA  * 3 + c) * G + iy) * G + ix;
        int baseB = ((bBt * 3 + c) * G + iy) * G + ix;
        xo[c]     = pack2(bilin(covP, baseA, G, wx, wy), bilin(covP, baseB, G, wx, wy));
        xo[3 + c] = pack2(bilin(varP, baseA, G, wx, wy), bilin(varP, baseB, G, wx, wy));
    }
}

// ---------------- kernel 3: per-pixel MLP, 2 batches packed in f32x2 ----------------
// Grid: (255 rows, 2 batch-pairs); 256 threads, t<255 = column.
__global__ __launch_bounds__(256) void mlp2_kernel(
    const float* __restrict__ w1, const float* __restrict__ g1, const float* __restrict__ b1,
    const float* __restrict__ rm1, const float* __restrict__ rv1,
    const float* __restrict__ w2, const float* __restrict__ g2, const float* __restrict__ b2,
    const float* __restrict__ rm2, const float* __restrict__ rv2,
    const float* __restrict__ w3) {

    __shared__ __align__(16) ull sW1d[48 * 24];   // {w,w} duplicated
    __shared__ __align__(16) ull sW2d[48 * 48];
    __shared__ __align__(16) ull sW3d[48 * 4];    // [o][p], p<3
    __shared__ ull sB1[48];
    __shared__ ull sB2[48];

    const int t = threadIdx.x;
    if (t < 48) {
        float inv1 = g1[t] * rsqrtf(rv1[t] + 1e-5f);
        float bb = fmaf(-rm1[t], inv1, b1[t]);
        sB1[t] = pack2(bb, bb);
        #pragma unroll
        for (int c = 0; c < 24; ++c) { float w = w1[t * 24 + c] * inv1; sW1d[t * 24 + c] = pack2(w, w); }
        float inv2 = g2[t] * rsqrtf(rv2[t] + 1e-5f);
        float bb2 = fmaf(-rm2[t], inv2, b2[t]);
        sB2[t] = pack2(bb2, bb2);
        #pragma unroll
        for (int c = 0; c < 48; ++c) { float w = w2[t * 48 + c] * inv2; sW2d[t * 48 + c] = pack2(w, w); }
        #pragma unroll
        for (int p = 0; p < 3; ++p) { float w = w3[p * 48 + t]; sW3d[t * 4 + p] = pack2(w, w); }
    }
    __syncthreads();
    if (t >= 255) return;

    const int i  = blockIdx.x;       // row in 255-grid
    const int bA = 2 * blockIdx.y;   // first batch of pair
    const int bBt = bA + 1;
    const int j  = t;

    ull x[24], mx1[3], my1[3];
    #pragma unroll
    for (int c = 0; c < 3; ++c) {
        int offA = (bA  * 3 + c) * G0 * G0 + i * G0 + j;
        int offB = (bBt * 3 + c) * G0 * G0 + i * G0 + j;
        float sgA  = dS0[0][offA] * (1.f/64.f), sgB  = dS0[0][offB] * (1.f/64.f);
        float ssA  = dS0[1][offA] * (1.f/64.f), ssB  = dS0[1][offB] * (1.f/64.f);
        float sggA = dS0[2][offA] * (1.f/64.f), sggB = dS0[2][offB] * (1.f/64.f);
        float sgsA = dS0[3][offA] * (1.f/64.f), sgsB = dS0[3][offB] * (1.f/64.f);
        mx1[c] = pack2(sgA, sgB);
        my1[c] = pack2(ssA, ssB);
        x[c]     = pack2(fmaf(-sgA, ssA, sgsA), fmaf(-sgB, ssB, sgsB));  // cov1
        x[3 + c] = pack2(fmaf(-sgA, sgA, sggA), fmaf(-sgB, sgB, sggB));  // var1
    }
    sampleLevel2(dF1[0], dF1[1], G1, bA, bBt, i, j, &x[6]);
    sampleLevel2(dF2[0], dF2[1], G2, bA, bBt, i, j, &x[12]);
    sampleLevel2(dF3[0], dF3[1], G3, bA, bBt, i, j, &x[18]);

    // layer 1: 24 -> 48, BN folded, relu (f32x2)
    ull h[48];
    #pragma unroll
    for (int o = 0; o < 48; ++o) {
        ull acc = sB1[o];
        const ulonglong2* wr = (const ulonglong2*)&sW1d[o * 24];
        #pragma unroll
        for (int c2 = 0; c2 < 12; ++c2) {
            ulonglong2 w = wr[c2];
            acc = fma2(w.x, x[2 * c2],     acc);
            acc = fma2(w.y, x[2 * c2 + 1], acc);
        }
        h[o] = relu2(acc);
    }
    // layers 2+3 fused: 48 -> 48 (relu) feeding 3 accumulators
    ull a3[3] = {0ull, 0ull, 0ull};
    #pragma unroll
    for (int o = 0; o < 48; ++o) {
        ull acc = sB2[o];
        const ulonglong2* wr = (const ulonglong2*)&sW2d[o * 48];
        #pragma unroll
        for (int c2 = 0; c2 < 24; ++c2) {
            ulonglong2 w = wr[c2];
            acc = fma2(w.x, h[2 * c2],     acc);
            acc = fma2(w.y, h[2 * c2 + 1], acc);
        }
        ull r = relu2(acc);
        a3[0] = fma2(sW3d[o * 4 + 0], r, a3[0]);
        a3[1] = fma2(sW3d[o * 4 + 1], r, a3[1]);
        a3[2] = fma2(sW3d[o * 4 + 2], r, a3[2]);
    }
    #pragma unroll
    for (int p = 0; p < 3; ++p) {
        float2 A  = unpack2(a3[p]);
        float2 mx = unpack2(mx1[p]);
        float2 my = unpack2(my1[p]);
        int offA = (bA  * 3 + p) * G0 * G0 + i * G0 + j;
        int offB = (bBt * 3 + p) * G0 * G0 + i * G0 + j;
        dAf[offA] = A.x; dCf[offA] = fmaf(-A.x, mx.x, my.x);
        dAf[offB] = A.y; dCf[offB] = fmaf(-A.y, mx.y, my.y);
    }
}

// ---------------- kernel 4: upsample A,b (255->1024, align_corners) + affine ----------------
__global__ __launch_bounds__(256) void final_kernel(const float* __restrict__ guide,
                                                    float* __restrict__ out) {
    __shared__ float sA[256];
    __shared__ float sC[256];
    const int y  = blockIdx.x;
    const int bc = blockIdx.y;
    const int t  = threadIdx.x;
    const float scale = (float)(254.0 / 1023.0);

    float py = y * scale;
    int iy = (int)py; if (iy > 253) iy = 253;
    float wy = py - iy;

    if (t < 255) {
        int b0 = bc * G0 * G0 + iy * G0 + t;
        float a0 = dAf[b0], a1 = dAf[b0 + G0];
        sA[t] = a0 + wy * (a1 - a0);
        float c0 = dCf[b0], c1 = dCf[b0 + G0];
        sC[t] = c0 + wy * (c1 - c0);
    }
    __syncthreads();

    size_t rowoff = ((size_t)bc * HH + y) * WW;
    float4 g = ((const float4*)(guide + rowoff))[t];
    float gv[4] = {g.x, g.y, g.z, g.w};
    float rv[4];
    #pragma unroll
    for (int k = 0; k < 4; ++k) {
        int xpix = 4 * t + k;
        float px = xpix * scale;
        int ix = (int)px; if (ix > 253) ix = 253;
        float wx = px - ix;
        float Av = sA[ix] + wx * (sA[ix + 1] - sA[ix]);
        float Cv = sC[ix] + wx * (sC[ix + 1] - sC[ix]);
        rv[k] = fmaf(Av, gv[k], Cv);
    }
    float4 r = {rv[0], rv[1], rv[2], rv[3]};
    ((float4*)(out + rowoff))[t] = r;
}

// ---------------- launch ----------------
extern "C" void kernel_launch(void* const* d_in, const int* in_sizes, int n_in,
                              void* d_out, int out_size) {
    const float* guide = (const float*)d_in[0];
    const float* src   = (const float*)d_in[1];
    const float* w1  = (const float*)d_in[2];
    const float* g1  = (const float*)d_in[3];
    const float* b1  = (const float*)d_in[4];
    const float* rm1 = (const float*)d_in[5];
    const float* rv1 = (const float*)d_in[6];
    const float* w2  = (const float*)d_in[7];
    const float* g2  = (const float*)d_in[8];
    const float* b2  = (const float*)d_in[9];
    const float* rm2 = (const float*)d_in[10];
    const float* rv2 = (const float*)d_in[11];
    const float* w3  = (const float*)d_in[12];
    float* out = (float*)d_out;

    boxsum_kernel<<<dim3(32, NBC), 256>>>(guide, src);
    pyr1_kernel<<<dim3((G1*G1 + 255) / 256, NBC), 256>>>();
    pyr23_kernel<<<NBC, 256>>>();
    mlp2_kernel<<<dim3(G0, BB/2), 256>>>(w1, g1, b1, rm1, rv1, w2, g2, b2, rm2, rv2, w3);
    final_kernel<<<dim3(HH, NBC), 256>>>(guide, out);
}

// round 3
// speedup vs baseline: 1.0925x; 1.0731x over previous
#include <cuda_runtime.h>
#include <math.h>

#define BB 4
#define CC 3
#define HH 1024
#define WW 1024
#define NBC 12          // B*C
#define G0 255
#define G1 127
#define G2 63
#define G3 31

typedef unsigned long long ull;

// ---------------- f32x2 helpers ----------------
__device__ __forceinline__ ull pack2(float lo, float hi) {
    ull r; asm("mov.b64 %0, {%1,%2};" : "=l"(r) : "f"(lo), "f"(hi)); return r;
}
__device__ __forceinline__ float2 unpack2(ull v) {
    float2 r; asm("mov.b64 {%0,%1}, %2;" : "=f"(r.x), "=f"(r.y) : "l"(v)); return r;
}
__device__ __forceinline__ ull fma2(ull a, ull b, ull c) {
    ull d; asm("fma.rn.f32x2 %0, %1, %2, %3;" : "=l"(d) : "l"(a), "l"(b), "l"(c)); return d;
}
__device__ __forceinline__ ull add2(ull a, ull b) {
    ull d; asm("add.rn.f32x2 %0, %1, %2;" : "=l"(d) : "l"(a), "l"(b)); return d;
}
__device__ __forceinline__ ull relu2(ull v) {
    float2 t = unpack2(v);
    return pack2(fmaxf(t.x, 0.f), fmaxf(t.y, 0.f));
}

// ---------------- scratch ----------------
__device__ float dS0[4][NBC*G0*G0];   // level-0 box sums: Sg, Ss, Sgg, Sgs
__device__ float dS1[4][NBC*G1*G1];
__device__ float dS2[4][NBC*G2*G2];
__device__ float dF1[2][NBC*G1*G1];
__device__ float dF2[2][NBC*G2*G2];
__device__ float dF3[2][NBC*G3*G3];
__device__ float dAf[NBC*G0*G0];      // A
__device__ float dCf[NBC*G0*G0];      // b = my1 - A*mx1
__device__ float dXf[BB*24*G0*256];   // features, [b][f][i][j(256 padded)]

// ---------------- kernel 1: level-0 box sums (r=8, s=4, VALID) ----------------
__global__ __launch_bounds__(256) void boxsum_kernel(const float* __restrict__ guide,
                                                     const float* __restrict__ src) {
    __shared__ __align__(16) float shg[4 * 1024];
    __shared__ __align__(16) float shs[4 * 1024];
    const int t  = threadIdx.x;
    const int bc = blockIdx.y;
    const int i0 = blockIdx.x * 8;
    const int i1 = min(i0 + 8, 255);

    const float* gbase = guide + (size_t)bc * HH * WW;
    const float* sbase = src   + (size_t)bc * HH * WW;

    float qg = 0.f, qs = 0.f, qgg = 0.f, qgs = 0.f;

    for (int m = i0; m <= i1; ++m) {
        const float4* gp = (const float4*)(gbase + (size_t)(4 * m) * WW);
        const float4* sp = (const float4*)(sbase + (size_t)(4 * m) * WW);
        float4* shg4 = (float4*)shg;
        float4* shs4 = (float4*)shs;
        #pragma unroll
        for (int k = 0; k < 4; ++k) {
            int idx = t + k * 256;
            shg4[idx] = gp[idx];
            shs4[idx] = sp[idx];
        }
        __syncthreads();

        if (t < 255) {
            float pg = 0.f, ps = 0.f, pgg = 0.f, pgs = 0.f;
            #pragma unroll
            for (int rr = 0; rr < 4; ++rr) {
                const float* g = shg + rr * 1024 + 4 * t;
                const float* s = shs + rr * 1024 + 4 * t;
                float4 ga = *(const float4*)(g);
                float4 gb = *(const float4*)(g + 4);
                float4 sa = *(const float4*)(s);
                float4 sb = *(const float4*)(s + 4);
                float gv[8] = {ga.x, ga.y, ga.z, ga.w, gb.x, gb.y, gb.z, gb.w};
                float sv[8] = {sa.x, sa.y, sa.z, sa.w, sb.x, sb.y, sb.z, sb.w};
                #pragma unroll
                for (int k = 0; k < 8; ++k) {
                    pg += gv[k];
                    ps += sv[k];
                    pgg = fmaf(gv[k], gv[k], pgg);
                    pgs = fmaf(gv[k], sv[k], pgs);
                }
            }
            if (m > i0) {
                int off = bc * G0 * G0 + (m - 1) * G0 + t;
                dS0[0][off] = qg + pg;
                dS0[1][off] = qs + ps;
                dS0[2][off] = qgg + pgg;
                dS0[3][off] = qgs + pgs;
            }
            qg = pg; qs = ps; qgg = pgg; qgs = pgs;
        }
        __syncthreads();
    }
}

// ---------------- pyramid ----------------
__device__ __forceinline__ void pyr_step(const float* __restrict__ in0, const float* __restrict__ in1,
                                         const float* __restrict__ in2, const float* __restrict__ in3,
                                         float* s0, float* s1, float* s2, float* s3,
                                         float* fcov, float* fvar,
                                         int GIN, int GOUT, float INVN, int bc, int idx) {
    int i = idx / GOUT, j = idx - i * GOUT;
    int p00 = bc * GIN * GIN + 2 * i * GIN + 2 * j;
    #define SUM4(p) ((p)[p00] + (p)[p00 + 2] + (p)[p00 + 2*GIN] + (p)[p00 + 2*GIN + 2])
    float sg  = SUM4(in0);
    float ss  = SUM4(in1);
    float sgg = SUM4(in2);
    float sgs = SUM4(in3);
    #undef SUM4
    int o = bc * GOUT * GOUT + idx;
    if (s0) { s0[o] = sg; s1[o] = ss; s2[o] = sgg; s3[o] = sgs; }
    float mx = sg * INVN, my = ss * INVN;
    fcov[o] = fmaf(-mx, my, sgs * INVN);
    fvar[o] = fmaf(-mx, mx, sgg * INVN);
}

__global__ __launch_bounds__(256) void pyr1_kernel() {
    int idx = blockIdx.x * blockDim.x + threadIdx.x;
    if (idx >= G1 * G1) return;
    pyr_step(dS0[0], dS0[1], dS0[2], dS0[3],
             dS1[0], dS1[1], dS1[2], dS1[3],
             dF1[0], dF1[1], G0, G1, 1.f/256.f, blockIdx.y, idx);
}

__global__ __launch_bounds__(256) void pyr23_kernel() {
    const int bc = blockIdx.x;
    for (int idx = threadIdx.x; idx < G2 * G2; idx += 256)
        pyr_step(dS1[0], dS1[1], dS1[2], dS1[3],
                 dS2[0], dS2[1], dS2[2], dS2[3],
                 dF2[0], dF2[1], G1, G2, 1.f/1024.f, bc, idx);
    __syncthreads();
    for (int idx = threadIdx.x; idx < G3 * G3; idx += 256)
        pyr_step(dS2[0], dS2[1], dS2[2], dS2[3],
                 (float*)0, (float*)0, (float*)0, (float*)0,
                 dF3[0], dF3[1], G2, G3, 1.f/4096.f, bc, idx);
}

// ---------------- bilinear ----------------
__device__ __forceinline__ float bilin(const float* __restrict__ p, int base, int G,
                                       float wx, float wy) {
    float v00 = p[base],     v01 = p[base + 1];
    float v10 = p[base + G], v11 = p[base + G + 1];
    float v0 = v00 + wx * (v01 - v00);
    float v1 = v10 + wx * (v11 - v10);
    return v0 + wy * (v1 - v0);
}

__device__ __forceinline__ void sampleLevel(const float* __restrict__ covP,
                                            const float* __restrict__ varP,
                                            int G, int b, int i, int j, float* xo) {
    float scale = (float)((double)(G - 1) / 254.0);
    float py = i * scale, px = j * scale;
    int iy = (int)py; if (iy > G - 2) iy = G - 2;
    int ix = (int)px; if (ix > G - 2) ix = G - 2;
    float wy = py - iy, wx = px - ix;
    #pragma unroll
    for (int c = 0; c < 3; ++c) {
        int base = ((b * 3 + c) * G + iy) * G + ix;
        xo[c]     = bilin(covP, base, G, wx, wy);
        xo[3 + c] = bilin(varP, base, G, wx, wy);
    }
}

// ---------------- kernel 3a: build features x[24] per pixel ----------------
__global__ __launch_bounds__(256) void featbuild_kernel() {
    const int t = threadIdx.x;
    const int i = blockIdx.x;   // row
    const int b = blockIdx.y;   // batch
    float x[24];
    if (t < 255) {
        const int j = t;
        #pragma unroll
        for (int c = 0; c < 3; ++c) {
            int off = (b * 3 + c) * G0 * G0 + i * G0 + j;
            float sg  = dS0[0][off] * (1.f/64.f);
            float ss  = dS0[1][off] * (1.f/64.f);
            float sgg = dS0[2][off] * (1.f/64.f);
            float sgs = dS0[3][off] * (1.f/64.f);
            x[c]     = fmaf(-sg, ss, sgs);
            x[3 + c] = fmaf(-sg, sg, sgg);
        }
        sampleLevel(dF1[0], dF1[1], G1, b, i, j, &x[6]);
        sampleLevel(dF2[0], dF2[1], G2, b, i, j, &x[12]);
        sampleLevel(dF3[0], dF3[1], G3, b, i, j, &x[18]);
    } else {
        #pragma unroll
        for (int f = 0; f < 24; ++f) x[f] = 0.f;
    }
    #pragma unroll
    for (int f = 0; f < 24; ++f)
        dXf[((b * 24 + f) * G0 + i) * 256 + t] = x[f];
}

// ---------------- kernel 3b: tiled GEMM MLP ----------------
// Block: 256 threads, tile = 256 pixels (one row i of one batch) x 48 outputs.
// Thread tile: 8 pixels x 6 outputs, f32x2-packed over pixel pairs.
// smem layout (bytes):
//   x_s   [24][260] f  @ 0       (24960)
//   h_s   [48][260] f  @ 24960   (49920)
//   w1d   [24][48] ull @ 74880   (9216)
//   w2d   [48][48] ull @ 84096   (18432)
//   w3d   [3][48]  ull @ 102528  (1152)
//   b1d   [48]     ull @ 103680  (384)
//   b2d   [48]     ull @ 104064  (384)
#define GEMM_SMEM 104448
#define XS_STRIDE 260

__global__ __launch_bounds__(256, 2) void gemm_kernel(
    const float* __restrict__ w1, const float* __restrict__ g1, const float* __restrict__ b1,
    const float* __restrict__ rm1, const float* __restrict__ rv1,
    const float* __restrict__ w2, const float* __restrict__ g2, const float* __restrict__ b2,
    const float* __restrict__ rm2, const float* __restrict__ rv2,
    const float* __restrict__ w3) {

    extern __shared__ __align__(16) char smem_raw[];
    float* x_s = (float*)smem_raw;
    float* h_s = (float*)(smem_raw + 24960);
    ull* w1d = (ull*)(smem_raw + 74880);
    ull* w2d = (ull*)(smem_raw + 84096);
    ull* w3d = (ull*)(smem_raw + 102528);
    ull* b1d = (ull*)(smem_raw + 103680);
    ull* b2d = (ull*)(smem_raw + 104064);

    const int t = threadIdx.x;
    const int i = blockIdx.x;   // row
    const int b = blockIdx.y;   // batch

    // ---- weight prep (folded BN, duplicated) ----
    if (t < 48) {
        float inv1 = g1[t] * rsqrtf(rv1[t] + 1e-5f);
        float bb1 = fmaf(-rm1[t], inv1, b1[t]);
        b1d[t] = pack2(bb1, bb1);
        #pragma unroll
        for (int c = 0; c < 24; ++c) {
            float w = w1[t * 24 + c] * inv1;
            w1d[c * 48 + t] = pack2(w, w);
        }
        float inv2 = g2[t] * rsqrtf(rv2[t] + 1e-5f);
        float bb2 = fmaf(-rm2[t], inv2, b2[t]);
        b2d[t] = pack2(bb2, bb2);
        #pragma unroll
        for (int c = 0; c < 48; ++c) {
            float w = w2[t * 48 + c] * inv2;
            w2d[c * 48 + t] = pack2(w, w);
        }
        #pragma unroll
        for (int cc = 0; cc < 3; ++cc) {
            float w = w3[cc * 48 + t];
            w3d[cc * 48 + t] = pack2(w, w);
        }
    }
    // ---- load x tile ----
    #pragma unroll
    for (int f = 0; f < 24; ++f)
        x_s[f * XS_STRIDE + t] = dXf[((b * 24 + f) * G0 + i) * 256 + t];
    __syncthreads();

    const int og = t & 7;          // output group
    const int pg = t >> 3;         // pixel group (0..31)
    const int o0 = og * 6;
    const int p0 = pg * 8;

    // ---- layer 1: 24 -> 48 ----
    ull acc[24];                    // [k][q] : 6 outputs x 4 pixel-pairs
    #pragma unroll
    for (int k = 0; k < 6; ++k) {
        ull bias = b1d[o0 + k];
        acc[k*4+0] = bias; acc[k*4+1] = bias; acc[k*4+2] = bias; acc[k*4+3] = bias;
    }
    #pragma unroll
    for (int c = 0; c < 24; ++c) {
        const ulonglong2* xr = (const ulonglong2*)&x_s[c * XS_STRIDE + p0];
        ulonglong2 xa = xr[0];
        ulonglong2 xb = xr[1];
        const ulonglong2* wr = (const ulonglong2*)&w1d[c * 48 + o0];
        ulonglong2 w01 = wr[0], w23 = wr[1], w45 = wr[2];
        ull wv[6] = {w01.x, w01.y, w23.x, w23.y, w45.x, w45.y};
        #pragma unroll
        for (int k = 0; k < 6; ++k) {
            acc[k*4+0] = fma2(wv[k], xa.x, acc[k*4+0]);
            acc[k*4+1] = fma2(wv[k], xa.y, acc[k*4+1]);
            acc[k*4+2] = fma2(wv[k], xb.x, acc[k*4+2]);
            acc[k*4+3] = fma2(wv[k], xb.y, acc[k*4+3]);
        }
    }
    // relu + store h
    #pragma unroll
    for (int k = 0; k < 6; ++k) {
        int o = o0 + k;
        ulonglong2* hp = (ulonglong2*)&h_s[o * XS_STRIDE + p0];
        ulonglong2 v0; v0.x = relu2(acc[k*4+0]); v0.y = relu2(acc[k*4+1]);
        ulonglong2 v1; v1.x = relu2(acc[k*4+2]); v1.y = relu2(acc[k*4+3]);
        hp[0] = v0; hp[1] = v1;
    }
    __syncthreads();

    // ---- layer 2: 48 -> 48 ----
    #pragma unroll
    for (int k = 0; k < 6; ++k) {
        ull bias = b2d[o0 + k];
        acc[k*4+0] = bias; acc[k*4+1] = bias; acc[k*4+2] = bias; acc[k*4+3] = bias;
    }
    #pragma unroll
    for (int c = 0; c < 48; ++c) {
        const ulonglong2* xr = (const ulonglong2*)&h_s[c * XS_STRIDE + p0];
        ulonglong2 xa = xr[0];
        ulonglong2 xb = xr[1];
        const ulonglong2* wr = (const ulonglong2*)&w2d[c * 48 + o0];
        ulonglong2 w01 = wr[0], w23 = wr[1], w45 = wr[2];
        ull wv[6] = {w01.x, w01.y, w23.x, w23.y, w45.x, w45.y};
        #pragma unroll
        for (int k = 0; k < 6; ++k) {
            acc[k*4+0] = fma2(wv[k], xa.x, acc[k*4+0]);
            acc[k*4+1] = fma2(wv[k], xa.y, acc[k*4+1]);
            acc[k*4+2] = fma2(wv[k], xb.x, acc[k*4+2]);
            acc[k*4+3] = fma2(wv[k], xb.y, acc[k*4+3]);
        }
    }
    // ---- layer 3 folded: relu(h2) -> 3 accumulators ----
    ull a3[12];                    // [cc][q]
    #pragma unroll
    for (int m = 0; m < 12; ++m) a3[m] = 0ull;
    #pragma unroll
    for (int k = 0; k < 6; ++k) {
        ull r0 = relu2(acc[k*4+0]);
        ull r1 = relu2(acc[k*4+1]);
        ull r2 = relu2(acc[k*4+2]);
        ull r3 = relu2(acc[k*4+3]);
        #pragma unroll
        for (int cc = 0; cc < 3; ++cc) {
            ull w = w3d[cc * 48 + o0 + k];
            a3[cc*4+0] = fma2(w, r0, a3[cc*4+0]);
            a3[cc*4+1] = fma2(w, r1, a3[cc*4+1]);
            a3[cc*4+2] = fma2(w, r2, a3[cc*4+2]);
            a3[cc*4+3] = fma2(w, r3, a3[cc*4+3]);
        }
    }
    // ---- reduce over the 8 output groups (consecutive lanes) ----
    #pragma unroll
    for (int m = 0; m < 12; ++m) {
        a3[m] = add2(a3[m], __shfl_xor_sync(0xffffffffu, a3[m], 1));
        a3[m] = add2(a3[m], __shfl_xor_sync(0xffffffffu, a3[m], 2));
        a3[m] = add2(a3[m], __shfl_xor_sync(0xffffffffu, a3[m], 4));
    }
    // ---- epilogue: lanes with og==0 write A and b ----
    if (og == 0) {
        #pragma unroll
        for (int cc = 0; cc < 3; ++cc) {
            int plane = (b * 3 + cc) * G0 * G0 + i * G0;
            #pragma unroll
            for (int q = 0; q < 4; ++q) {
                float2 A = unpack2(a3[cc*4+q]);
                int j0 = p0 + 2 * q;
                {
                    float mx = dS0[0][plane + j0] * (1.f/64.f);
                    float my = dS0[1][plane + j0] * (1.f/64.f);
                    dAf[plane + j0] = A.x;
                    dCf[plane + j0] = fmaf(-A.x, mx, my);
                }
                if (j0 + 1 < G0) {
                    float mx = dS0[0][plane + j0 + 1] * (1.f/64.f);
                    float my = dS0[1][plane + j0 + 1] * (1.f/64.f);
                    dAf[plane + j0 + 1] = A.y;
                    dCf[plane + j0 + 1] = fmaf(-A.y, mx, my);
                }
            }
        }
    }
}

// ---------------- kernel 4: upsample A,b + affine ----------------
__global__ __launch_bounds__(256) void final_kernel(const float* __restrict__ guide,
                                                    float* __restrict__ out) {
    __shared__ float sA[256];
    __shared__ float sC[256];
    const int y  = blockIdx.x;
    const int bc = blockIdx.y;
    const int t  = threadIdx.x;
    const float scale = (float)(254.0 / 1023.0);

    float py = y * scale;
    int iy = (int)py; if (iy > 253) iy = 253;
    float wy = py - iy;

    if (t < 255) {
        int b0 = bc * G0 * G0 + iy * G0 + t;
        float a0 = dAf[b0], a1 = dAf[b0 + G0];
        sA[t] = a0 + wy * (a1 - a0);
        float c0 = dCf[b0], c1 = dCf[b0 + G0];
        sC[t] = c0 + wy * (c1 - c0);
    }
    __syncthreads();

    size_t rowoff = ((size_t)bc * HH + y) * WW;
    float4 g = ((const float4*)(guide + rowoff))[t];
    float gv[4] = {g.x, g.y, g.z, g.w};
    float rv[4];
    #pragma unroll
    for (int k = 0; k < 4; ++k) {
        int xpix = 4 * t + k;
        float px = xpix * scale;
        int ix = (int)px; if (ix > 253) ix = 253;
        float wx = px - ix;
        float Av = sA[ix] + wx * (sA[ix + 1] - sA[ix]);
        float Cv = sC[ix] + wx * (sC[ix + 1] - sC[ix]);
        rv[k] = fmaf(Av, gv[k], Cv);
    }
    float4 r = {rv[0], rv[1], rv[2], rv[3]};
    ((float4*)(out + rowoff))[t] = r;
}

// ---------------- launch ----------------
extern "C" void kernel_launch(void* const* d_in, const int* in_sizes, int n_in,
                              void* d_out, int out_size) {
    const float* guide = (const float*)d_in[0];
    const float* src   = (const float*)d_in[1];
    const float* w1  = (const float*)d_in[2];
    const float* g1  = (const float*)d_in[3];
    const float* b1  = (const float*)d_in[4];
    const float* rm1 = (const float*)d_in[5];
    const float* rv1 = (const float*)d_in[6];
    const float* w2  = (const float*)d_in[7];
    const float* g2  = (const float*)d_in[8];
    const float* b2  = (const float*)d_in[9];
    const float* rm2 = (const float*)d_in[10];
    const float* rv2 = (const float*)d_in[11];
    const float* w3  = (const float*)d_in[12];
    float* out = (float*)d_out;

    cudaFuncSetAttribute(gemm_kernel, cudaFuncAttributeMaxDynamicSharedMemorySize, GEMM_SMEM);

    boxsum_kernel<<<dim3(32, NBC), 256>>>(guide, src);
    pyr1_kernel<<<dim3((G1*G1 + 255) / 256, NBC), 256>>>();
    pyr23_kernel<<<NBC, 256>>>();
    featbuild_kernel<<<dim3(G0, BB), 256>>>();
    gemm_kernel<<<dim3(G0, BB), 256, GEMM_SMEM>>>(w1, g1, b1, rm1, rv1, w2, g2, b2, rm2, rv2, w3);
    final_kernel<<<dim3(HH, NBC), 256>>>(guide, out);
}